// round 7
// baseline (speedup 1.0000x reference)
#include <cuda_runtime.h>
#include <cstdint>
#include <cstddef>

// ---------------------------------------------------------------------------
// Problem dims
// ---------------------------------------------------------------------------
#define NROWS 16384
#define INF   512
#define OUTF  256

// GEMM tiling
#define TILE_M 128
#define TILE_N 256
#define KC     32            // K elems per pipeline stage
#define PITCH  36            // smem row pitch in floats (32 + 4 pad): bank = (4g+t)&31, conflict-free
#define A_SM_FLOATS (TILE_M * PITCH)                 // 4608
#define B_SM_FLOATS (TILE_N * PITCH)                 // 9216
#define STAGE_FLOATS (A_SM_FLOATS + B_SM_FLOATS)     // 13824
#define NSTAGE 3
#define SMEM_BYTES (NSTAGE * STAGE_FLOATS * 4)       // 165888

// ---------------------------------------------------------------------------
// Scratch (__device__ globals: allocation-free)
// ---------------------------------------------------------------------------
__device__ __align__(256) float g_dhf[(size_t)NROWS * INF];   // hat_d*feature, tf32-rounded (32 MB)
__device__ __align__(256) float g_wrn[(size_t)OUTF * INF];    // W, tf32-rounded (0.5 MB)
__device__ __align__(256) float g_gT [(size_t)OUTF * NROWS];  // g^T [256][16384], tf32-rounded (16 MB)

// ---------------------------------------------------------------------------
// Helpers
// ---------------------------------------------------------------------------
__device__ __forceinline__ uint32_t smem_u32(const void* p) {
    uint32_t a;
    asm("{ .reg .u64 t; cvta.to.shared.u64 t, %1; cvt.u32.u64 %0, t; }" : "=r"(a) : "l"(p));
    return a;
}

__device__ __forceinline__ float rna_tf32(float x) {
    uint32_t u;
    asm("cvt.rna.tf32.f32 %0, %1;" : "=r"(u) : "f"(x));
    return __uint_as_float(u);
}

__device__ __forceinline__ void cp16(uint32_t dst_smem, const float* src) {
    asm volatile("cp.async.cg.shared.global [%0], [%1], 16;"
                 :: "r"(dst_smem), "l"(src) : "memory");
}

__device__ __forceinline__ void mma_tf32(float* d, const uint32_t* a, const uint32_t* b) {
    asm volatile(
        "mma.sync.aligned.m16n8k8.row.col.f32.tf32.tf32.f32 "
        "{%0,%1,%2,%3}, {%4,%5,%6,%7}, {%8,%9}, {%0,%1,%2,%3};"
        : "+f"(d[0]), "+f"(d[1]), "+f"(d[2]), "+f"(d[3])
        : "r"(a[0]), "r"(a[1]), "r"(a[2]), "r"(a[3]),
          "r"(b[0]), "r"(b[1]));
}

// ---------------------------------------------------------------------------
// Prep: dhf = rna(hat_d * feature); wrn = rna(W)
// ---------------------------------------------------------------------------
__global__ void prep_kernel(const float* __restrict__ hat_d,
                            const float* __restrict__ feature,
                            const float* __restrict__ W) {
    size_t i = (size_t)blockIdx.x * blockDim.x + threadIdx.x;
    size_t stride = (size_t)gridDim.x * blockDim.x;

    const float4* f4 = reinterpret_cast<const float4*>(feature);
    float4* d4 = reinterpret_cast<float4*>(g_dhf);
    size_t total4 = (size_t)NROWS * INF / 4;
    for (size_t idx = i; idx < total4; idx += stride) {
        float4 f = f4[idx];
        float d = __ldg(hat_d + (idx >> 7));   // (idx*4)/512
        float4 o;
        o.x = rna_tf32(d * f.x);
        o.y = rna_tf32(d * f.y);
        o.z = rna_tf32(d * f.z);
        o.w = rna_tf32(d * f.w);
        d4[idx] = o;
    }

    const float4* w4 = reinterpret_cast<const float4*>(W);
    float4* wr4 = reinterpret_cast<float4*>(g_wrn);
    size_t wtotal4 = (size_t)OUTF * INF / 4;
    for (size_t idx = i; idx < wtotal4; idx += stride) {
        float4 f = w4[idx];
        float4 o;
        o.x = rna_tf32(f.x);
        o.y = rna_tf32(f.y);
        o.z = rna_tf32(f.z);
        o.w = rna_tf32(f.w);
        wr4[idx] = o;
    }
}

// ---------------------------------------------------------------------------
// tf32 mma.sync GEMM: D[128 x 256] = Atile[128 x K] @ Bp[256 x K]^T
//   Bp rows are the N dimension (K contiguous within a row).
//   mode 0: g_gT[n][m] = rna(D[m][n])                       (GEMM1)
//   mode 1: out[m][n]  = hat_d[m]*(D[m][n] + gT[n][m]) + b[n] (GEMM2)
// 512 threads = 16 warps in 4x4 grid; warp tile 32(M) x 64(N).
// ---------------------------------------------------------------------------
__global__ void __launch_bounds__(512, 1)
gemm_tf32_kernel(const float* __restrict__ Ap, int a_ld,
                 const float* __restrict__ Bp, int b_ld,
                 int nstages, int mode,
                 const float* __restrict__ hat_d,
                 const float* __restrict__ bias,
                 float* __restrict__ out)
{
    extern __shared__ float sm[];
    const int tid = threadIdx.x;
    const int mtile = blockIdx.x;
    const int wid = tid >> 5;
    const int lane = tid & 31;
    const int wm = wid >> 2;          // 0..3: M position (32 rows each)
    const int wn = wid & 3;           // 0..3: N position (64 cols each)
    const int g = lane >> 2;          // groupID 0..7
    const int t = lane & 3;           // threadID in group 0..3

    float acc[2][8][4];
    #pragma unroll
    for (int mi = 0; mi < 2; ++mi)
        #pragma unroll
        for (int ni = 0; ni < 8; ++ni)
            #pragma unroll
            for (int r = 0; r < 4; ++r)
                acc[mi][ni][r] = 0.0f;

    const float* Agm = Ap + (size_t)mtile * TILE_M * a_ld;

    // ---- stage loader: 1024 A-float4s + 2048 B-float4s across 512 threads ----
    auto load_stage = [&](int s) {
        const int buf = s % NSTAGE;
        float* As = sm + buf * STAGE_FLOATS;
        float* Bs = As + A_SM_FLOATS;
        const int k0 = s * KC;
        #pragma unroll
        for (int i = 0; i < 2; ++i) {
            int v = tid + i * 512;
            int row = v >> 3, j = v & 7;
            cp16(smem_u32(As + row * PITCH + j * 4),
                 Agm + (size_t)row * a_ld + k0 + j * 4);
        }
        #pragma unroll
        for (int i = 0; i < 4; ++i) {
            int v = tid + i * 512;
            int row = v >> 3, j = v & 7;
            cp16(smem_u32(Bs + row * PITCH + j * 4),
                 Bp + (size_t)row * b_ld + k0 + j * 4);
        }
    };

    // prologue: 2 stages in flight
    load_stage(0);
    asm volatile("cp.async.commit_group;" ::: "memory");
    load_stage(1);
    asm volatile("cp.async.commit_group;" ::: "memory");

    for (int s = 0; s < nstages; ++s) {
        asm volatile("cp.async.wait_group 1;" ::: "memory");
        __syncthreads();                       // stage s visible to all; prev compute done

        if (s + 2 < nstages) load_stage(s + 2);
        asm volatile("cp.async.commit_group;" ::: "memory");  // empty group if no load: keeps counting uniform

        const int buf = s % NSTAGE;
        const float* As = sm + buf * STAGE_FLOATS;
        const float* Bs = As + A_SM_FLOATS;
        const float* Abase = As + (wm * 32 + g) * PITCH + t;
        const float* Bbase = Bs + (wn * 64 + g) * PITCH + t;

        #pragma unroll
        for (int kk = 0; kk < KC; kk += 8) {
            uint32_t a[2][4], b[8][2];
            #pragma unroll
            for (int mi = 0; mi < 2; ++mi) {
                const float* p = Abase + mi * 16 * PITCH + kk;
                a[mi][0] = __float_as_uint(p[0]);
                a[mi][1] = __float_as_uint(p[8 * PITCH]);
                a[mi][2] = __float_as_uint(p[4]);
                a[mi][3] = __float_as_uint(p[8 * PITCH + 4]);
            }
            #pragma unroll
            for (int ni = 0; ni < 8; ++ni) {
                const float* p = Bbase + ni * 8 * PITCH + kk;
                b[ni][0] = __float_as_uint(p[0]);
                b[ni][1] = __float_as_uint(p[4]);
            }
            #pragma unroll
            for (int mi = 0; mi < 2; ++mi)
                #pragma unroll
                for (int ni = 0; ni < 8; ++ni)
                    mma_tf32(acc[mi][ni], a[mi], b[ni]);
        }
    }

    // ---- epilogue ----
    const int mbase = mtile * TILE_M + wm * 32;
    const int nbase = wn * 64;

    if (mode == 0) {
        #pragma unroll
        for (int mi = 0; mi < 2; ++mi) {
            int r0 = mbase + mi * 16 + g;
            int r1 = r0 + 8;
            #pragma unroll
            for (int ni = 0; ni < 8; ++ni) {
                int c0 = nbase + ni * 8 + 2 * t;
                int c1 = c0 + 1;
                g_gT[(size_t)c0 * NROWS + r0] = rna_tf32(acc[mi][ni][0]);
                g_gT[(size_t)c1 * NROWS + r0] = rna_tf32(acc[mi][ni][1]);
                g_gT[(size_t)c0 * NROWS + r1] = rna_tf32(acc[mi][ni][2]);
                g_gT[(size_t)c1 * NROWS + r1] = rna_tf32(acc[mi][ni][3]);
            }
        }
    } else {
        #pragma unroll
        for (int mi = 0; mi < 2; ++mi) {
            int r0 = mbase + mi * 16 + g;
            int r1 = r0 + 8;
            float h0 = __ldg(hat_d + r0);
            float h1 = __ldg(hat_d + r1);
            #pragma unroll
            for (int ni = 0; ni < 8; ++ni) {
                int c0 = nbase + ni * 8 + 2 * t;
                int c1 = c0 + 1;
                float b0v = __ldg(bias + c0);
                float b1v = __ldg(bias + c1);
                float g00 = g_gT[(size_t)c0 * NROWS + r0];
                float g01 = g_gT[(size_t)c1 * NROWS + r0];
                float g10 = g_gT[(size_t)c0 * NROWS + r1];
                float g11 = g_gT[(size_t)c1 * NROWS + r1];
                float2 v0, v1;
                v0.x = fmaf(h0, acc[mi][ni][0] + g00, b0v);
                v0.y = fmaf(h0, acc[mi][ni][1] + g01, b1v);
                v1.x = fmaf(h1, acc[mi][ni][2] + g10, b0v);
                v1.y = fmaf(h1, acc[mi][ni][3] + g11, b1v);
                *reinterpret_cast<float2*>(out + (size_t)r0 * OUTF + c0) = v0;
                *reinterpret_cast<float2*>(out + (size_t)r1 * OUTF + c0) = v1;
            }
        }
    }
}

// ---------------------------------------------------------------------------
// Host side
// ---------------------------------------------------------------------------
extern "C" void kernel_launch(void* const* d_in, const int* in_sizes, int n_in,
                              void* d_out, int out_size) {
    const float *A = nullptr, *hat_d = nullptr, *feature = nullptr,
                *W = nullptr, *b = nullptr;
    for (int i = 0; i < n_in; ++i) {
        switch (in_sizes[i]) {
            case NROWS:       hat_d   = (const float*)d_in[i]; break;   // 16384
            case OUTF:        b       = (const float*)d_in[i]; break;   // 256
            case OUTF * INF:  W       = (const float*)d_in[i]; break;   // 131072
            case NROWS * INF: feature = (const float*)d_in[i]; break;   // 8388608
            default:          A       = (const float*)d_in[i]; break;   // 16384*16384
        }
    }

    void *p_dhf = nullptr, *p_wrn = nullptr, *p_gT = nullptr;
    cudaGetSymbolAddress(&p_dhf, g_dhf);
    cudaGetSymbolAddress(&p_wrn, g_wrn);
    cudaGetSymbolAddress(&p_gT,  g_gT);

    static bool attr_set = false;
    if (!attr_set) {
        cudaFuncSetAttribute(gemm_tf32_kernel,
                             cudaFuncAttributeMaxDynamicSharedMemorySize, SMEM_BYTES);
        attr_set = true;
    }

    prep_kernel<<<1024, 256>>>(hat_d, feature, W);

    // GEMM1: g^T = (dhf @ W^T)^T   K = 512 -> 16 stages
    gemm_tf32_kernel<<<NROWS / TILE_M, 512, SMEM_BYTES>>>(
        (const float*)p_dhf, INF,
        (const float*)p_wrn, INF,
        INF / KC, 0, nullptr, nullptr, nullptr);

    // GEMM2: out = hat_d*(A@g + g) + b   K = 16384 -> 512 stages
    gemm_tf32_kernel<<<NROWS / TILE_M, 512, SMEM_BYTES>>>(
        A, NROWS,
        (const float*)p_gT, NROWS,
        NROWS / KC, 1, hat_d, b, (float*)d_out);

    (void)out_size;
}

// round 8
// speedup vs baseline: 1.0119x; 1.0119x over previous
#include <cuda_runtime.h>
#include <cstdint>
#include <cstddef>

// ---------------------------------------------------------------------------
// Problem dims
// ---------------------------------------------------------------------------
#define NROWS 16384
#define INF   512
#define OUTF  256

// GEMM tiling
#define TILE_M 128
#define TILE_N 256
#define KC     32            // K elems per pipeline stage
#define PA     36            // A smem row pitch (floats): LDS.32 bank = (4g+t)&31, conflict-free
#define PB     40            // B smem row pitch (floats): LDS.64 bankpair = (4g+t)&15 per half-warp, conflict-free
#define A_SM_FLOATS (TILE_M * PA)                    // 4608
#define B_SM_FLOATS (TILE_N * PB)                    // 10240
#define STAGE_FLOATS (A_SM_FLOATS + B_SM_FLOATS)     // 14848
#define NSTAGE 3
#define SMEM_BYTES (NSTAGE * STAGE_FLOATS * 4)       // 178176

// within-8-block k permutation: logical k -> physical offset
// off(k) = 2*(k&3) + ((k>>2)&1)   (so logical pair (t, t+4) sits at (2t, 2t+1))
__host__ __device__ __forceinline__ int kperm8(int k) {
    return 2 * (k & 3) + ((k >> 2) & 1);
}

// ---------------------------------------------------------------------------
// Scratch (__device__ globals: allocation-free)
// ---------------------------------------------------------------------------
__device__ __align__(256) float g_dhf[(size_t)NROWS * INF];   // hat_d*feature, tf32-rounded (32 MB)
__device__ __align__(256) float g_wrn[(size_t)OUTF * INF];    // W, tf32-rounded, k-permuted (0.5 MB)
__device__ __align__(256) float g_gT [(size_t)OUTF * NROWS];  // g^T [256][16384], tf32, k-permuted (16 MB)

// ---------------------------------------------------------------------------
// Helpers
// ---------------------------------------------------------------------------
__device__ __forceinline__ uint32_t smem_u32(const void* p) {
    uint32_t a;
    asm("{ .reg .u64 t; cvta.to.shared.u64 t, %1; cvt.u32.u64 %0, t; }" : "=r"(a) : "l"(p));
    return a;
}

__device__ __forceinline__ float rna_tf32(float x) {
    uint32_t u;
    asm("cvt.rna.tf32.f32 %0, %1;" : "=r"(u) : "f"(x));
    return __uint_as_float(u);
}

__device__ __forceinline__ void cp16(uint32_t dst_smem, const float* src) {
    asm volatile("cp.async.cg.shared.global [%0], [%1], 16;"
                 :: "r"(dst_smem), "l"(src) : "memory");
}

__device__ __forceinline__ void mma_tf32(float* d, const uint32_t* a, const uint32_t* b) {
    asm volatile(
        "mma.sync.aligned.m16n8k8.row.col.f32.tf32.tf32.f32 "
        "{%0,%1,%2,%3}, {%4,%5,%6,%7}, {%8,%9}, {%0,%1,%2,%3};"
        : "+f"(d[0]), "+f"(d[1]), "+f"(d[2]), "+f"(d[3])
        : "r"(a[0]), "r"(a[1]), "r"(a[2]), "r"(a[3]),
          "r"(b[0]), "r"(b[1]));
}

// ---------------------------------------------------------------------------
// Prep: dhf = rna(hat_d * feature);  wrn[r][kperm] = rna(W[r][k])
// ---------------------------------------------------------------------------
__global__ void prep_kernel(const float* __restrict__ hat_d,
                            const float* __restrict__ feature,
                            const float* __restrict__ W) {
    size_t i = (size_t)blockIdx.x * blockDim.x + threadIdx.x;
    size_t stride = (size_t)gridDim.x * blockDim.x;

    const float4* f4 = reinterpret_cast<const float4*>(feature);
    float4* d4 = reinterpret_cast<float4*>(g_dhf);
    size_t total4 = (size_t)NROWS * INF / 4;
    for (size_t idx = i; idx < total4; idx += stride) {
        float4 f = f4[idx];
        float d = __ldg(hat_d + (idx >> 7));   // (idx*4)/512
        float4 o;
        o.x = rna_tf32(d * f.x);
        o.y = rna_tf32(d * f.y);
        o.z = rna_tf32(d * f.z);
        o.w = rna_tf32(d * f.w);
        d4[idx] = o;
    }

    // W: small; scalar loop with k-permutation within 8-blocks
    size_t wtotal = (size_t)OUTF * INF;
    for (size_t idx = i; idx < wtotal; idx += stride) {
        int k = (int)(idx & (INF - 1));
        size_t row = idx >> 9;   // / INF
        int kp = (k & ~7) | kperm8(k & 7);
        g_wrn[row * INF + kp] = rna_tf32(W[idx]);
    }
}

// ---------------------------------------------------------------------------
// tf32 mma.sync GEMM: D[128 x 256] = Atile[128 x K] @ Bp[256 x K]^T
//   Bp (global) is k-PERMUTED within 8-blocks; A natural.
//   mode 0: g_gT[n][perm(m)] = rna(D[m][n])                        (GEMM1)
//   mode 1: out[m][n] = hat_d[m]*(D[m][n] + gT[n][perm(m)]) + b[n] (GEMM2)
// 512 threads = 16 warps in 4x4 grid; warp tile 32(M) x 64(N).
// ---------------------------------------------------------------------------
__global__ void __launch_bounds__(512, 1)
gemm_tf32_kernel(const float* __restrict__ Ap, int a_ld,
                 const float* __restrict__ Bp, int b_ld,
                 int nstages, int mode,
                 const float* __restrict__ hat_d,
                 const float* __restrict__ bias,
                 float* __restrict__ out)
{
    extern __shared__ float sm[];
    const int tid = threadIdx.x;
    const int mtile = blockIdx.x;
    const int wid = tid >> 5;
    const int lane = tid & 31;
    const int wm = wid >> 2;          // 0..3: M position (32 rows each)
    const int wn = wid & 3;           // 0..3: N position (64 cols each)
    const int g = lane >> 2;          // groupID 0..7
    const int t = lane & 3;           // threadID in group 0..3

    float acc[2][8][4];
    #pragma unroll
    for (int mi = 0; mi < 2; ++mi)
        #pragma unroll
        for (int ni = 0; ni < 8; ++ni)
            #pragma unroll
            for (int r = 0; r < 4; ++r)
                acc[mi][ni][r] = 0.0f;

    const float* Agm = Ap + (size_t)mtile * TILE_M * a_ld;

    // ---- stage loader: A 1024 float4s + B 2048 float4s across 512 threads ----
    auto load_stage = [&](int s) {
        const int buf = s % NSTAGE;
        float* As = sm + buf * STAGE_FLOATS;
        float* Bs = As + A_SM_FLOATS;
        const int k0 = s * KC;
        #pragma unroll
        for (int i = 0; i < 2; ++i) {
            int v = tid + i * 512;
            int row = v >> 3, j = v & 7;
            cp16(smem_u32(As + row * PA + j * 4),
                 Agm + (size_t)row * a_ld + k0 + j * 4);
        }
        #pragma unroll
        for (int i = 0; i < 4; ++i) {
            int v = tid + i * 512;
            int row = v >> 3, j = v & 7;
            cp16(smem_u32(Bs + row * PB + j * 4),
                 Bp + (size_t)row * b_ld + k0 + j * 4);
        }
    };

    // prologue: 2 stages in flight
    load_stage(0);
    asm volatile("cp.async.commit_group;" ::: "memory");
    load_stage(1);
    asm volatile("cp.async.commit_group;" ::: "memory");

    for (int s = 0; s < nstages; ++s) {
        asm volatile("cp.async.wait_group 1;" ::: "memory");
        __syncthreads();

        if (s + 2 < nstages) load_stage(s + 2);
        asm volatile("cp.async.commit_group;" ::: "memory");

        const int buf = s % NSTAGE;
        const float* As = sm + buf * STAGE_FLOATS;
        const float* Bs = As + A_SM_FLOATS;
        const float* Abase = As + (wm * 32 + g) * PA + t;
        const float* Bbase = Bs + (wn * 64 + g) * PB + 2 * t;

        // double-buffered fragments over 4 k-steps of 8
        uint32_t afr[2][2][4];
        uint32_t bfr[2][8][2];

        // load kk=0 into buf 0
        #pragma unroll
        for (int mi = 0; mi < 2; ++mi) {
            const float* p = Abase + mi * 16 * PA;
            afr[0][mi][0] = __float_as_uint(p[0]);
            afr[0][mi][1] = __float_as_uint(p[8 * PA]);
            afr[0][mi][2] = __float_as_uint(p[4]);
            afr[0][mi][3] = __float_as_uint(p[8 * PA + 4]);
        }
        #pragma unroll
        for (int ni = 0; ni < 8; ++ni) {
            float2 v = *reinterpret_cast<const float2*>(Bbase + ni * 8 * PB);
            bfr[0][ni][0] = __float_as_uint(v.x);
            bfr[0][ni][1] = __float_as_uint(v.y);
        }

        #pragma unroll
        for (int kk = 0; kk < 4; ++kk) {
            const int cb = kk & 1;
            if (kk < 3) {
                const int nb = (kk + 1) & 1;
                const int ko = (kk + 1) * 8;
                #pragma unroll
                for (int mi = 0; mi < 2; ++mi) {
                    const float* p = Abase + mi * 16 * PA + ko;
                    afr[nb][mi][0] = __float_as_uint(p[0]);
                    afr[nb][mi][1] = __float_as_uint(p[8 * PA]);
                    afr[nb][mi][2] = __float_as_uint(p[4]);
                    afr[nb][mi][3] = __float_as_uint(p[8 * PA + 4]);
                }
                #pragma unroll
                for (int ni = 0; ni < 8; ++ni) {
                    float2 v = *reinterpret_cast<const float2*>(Bbase + ni * 8 * PB + ko);
                    bfr[nb][ni][0] = __float_as_uint(v.x);
                    bfr[nb][ni][1] = __float_as_uint(v.y);
                }
            }
            #pragma unroll
            for (int mi = 0; mi < 2; ++mi)
                #pragma unroll
                for (int ni = 0; ni < 8; ++ni)
                    mma_tf32(acc[mi][ni], afr[cb][mi], bfr[cb][ni]);
        }
    }

    // ---- epilogue ----
    const int mbase = mtile * TILE_M + wm * 32;
    const int nbase = wn * 64;
    const int pg = kperm8(g);   // permuted within-8-block offset for row index

    if (mode == 0) {
        #pragma unroll
        for (int mi = 0; mi < 2; ++mi) {
            int r0p = mbase + mi * 16 + pg;   // (mbase+mi*16) is 8-aligned
            int r1p = r0p + 8;
            #pragma unroll
            for (int ni = 0; ni < 8; ++ni) {
                int c0 = nbase + ni * 8 + 2 * t;
                int c1 = c0 + 1;
                g_gT[(size_t)c0 * NROWS + r0p] = rna_tf32(acc[mi][ni][0]);
                g_gT[(size_t)c1 * NROWS + r0p] = rna_tf32(acc[mi][ni][1]);
                g_gT[(size_t)c0 * NROWS + r1p] = rna_tf32(acc[mi][ni][2]);
                g_gT[(size_t)c1 * NROWS + r1p] = rna_tf32(acc[mi][ni][3]);
            }
        }
    } else {
        #pragma unroll
        for (int mi = 0; mi < 2; ++mi) {
            int r0 = mbase + mi * 16 + g;     // logical output row
            int r1 = r0 + 8;
            int r0p = mbase + mi * 16 + pg;   // permuted gT column
            int r1p = r0p + 8;
            float h0 = __ldg(hat_d + r0);
            float h1 = __ldg(hat_d + r1);
            #pragma unroll
            for (int ni = 0; ni < 8; ++ni) {
                int c0 = nbase + ni * 8 + 2 * t;
                int c1 = c0 + 1;
                float b0v = __ldg(bias + c0);
                float b1v = __ldg(bias + c1);
                float g00 = g_gT[(size_t)c0 * NROWS + r0p];
                float g01 = g_gT[(size_t)c1 * NROWS + r0p];
                float g10 = g_gT[(size_t)c0 * NROWS + r1p];
                float g11 = g_gT[(size_t)c1 * NROWS + r1p];
                float2 v0, v1;
                v0.x = fmaf(h0, acc[mi][ni][0] + g00, b0v);
                v0.y = fmaf(h0, acc[mi][ni][1] + g01, b1v);
                v1.x = fmaf(h1, acc[mi][ni][2] + g10, b0v);
                v1.y = fmaf(h1, acc[mi][ni][3] + g11, b1v);
                *reinterpret_cast<float2*>(out + (size_t)r0 * OUTF + c0) = v0;
                *reinterpret_cast<float2*>(out + (size_t)r1 * OUTF + c0) = v1;
            }
        }
    }
}

// ---------------------------------------------------------------------------
// Host side
// ---------------------------------------------------------------------------
extern "C" void kernel_launch(void* const* d_in, const int* in_sizes, int n_in,
                              void* d_out, int out_size) {
    const float *A = nullptr, *hat_d = nullptr, *feature = nullptr,
                *W = nullptr, *b = nullptr;
    for (int i = 0; i < n_in; ++i) {
        switch (in_sizes[i]) {
            case NROWS:       hat_d   = (const float*)d_in[i]; break;   // 16384
            case OUTF:        b       = (const float*)d_in[i]; break;   // 256
            case OUTF * INF:  W       = (const float*)d_in[i]; break;   // 131072
            case NROWS * INF: feature = (const float*)d_in[i]; break;   // 8388608
            default:          A       = (const float*)d_in[i]; break;   // 16384*16384
        }
    }

    void *p_dhf = nullptr, *p_wrn = nullptr, *p_gT = nullptr;
    cudaGetSymbolAddress(&p_dhf, g_dhf);
    cudaGetSymbolAddress(&p_wrn, g_wrn);
    cudaGetSymbolAddress(&p_gT,  g_gT);

    static bool attr_set = false;
    if (!attr_set) {
        cudaFuncSetAttribute(gemm_tf32_kernel,
                             cudaFuncAttributeMaxDynamicSharedMemorySize, SMEM_BYTES);
        attr_set = true;
    }

    prep_kernel<<<1024, 256>>>(hat_d, feature, W);

    // GEMM1: g^T = (dhf @ W^T)^T   K = 512 -> 16 stages  (B = wrn, k-permuted)
    gemm_tf32_kernel<<<NROWS / TILE_M, 512, SMEM_BYTES>>>(
        (const float*)p_dhf, INF,
        (const float*)p_wrn, INF,
        INF / KC, 0, nullptr, nullptr, nullptr);

    // GEMM2: out = hat_d*(A@g + g) + b   K = 16384 -> 512 stages  (B = gT, k-permuted)
    gemm_tf32_kernel<<<NROWS / TILE_M, 512, SMEM_BYTES>>>(
        A, NROWS,
        (const float*)p_gT, NROWS,
        NROWS / KC, 1, hat_d, b, (float*)d_out);

    (void)out_size;
}

// round 9
// speedup vs baseline: 1.0776x; 1.0650x over previous
#include <cuda_runtime.h>
#include <cstdint>
#include <cstddef>

// ---------------------------------------------------------------------------
// Problem dims
// ---------------------------------------------------------------------------
#define NROWS 16384
#define INF   512
#define OUTF  256

// GEMM tiling: CTA tile 128(M) x 128(N), 2 CTAs per SM
#define TILE_M 128
#define TILE_N 128
#define KC     32            // K elems per pipeline stage
#define PA     36            // A smem pitch (floats): LDS.32 bank = (4g+t)&31 distinct
#define PB     40            // B smem pitch (floats): LDS.64 conflict-free per half-warp
#define A_SM_FLOATS (TILE_M * PA)                    // 4608
#define B_SM_FLOATS (TILE_N * PB)                    // 5120
#define STAGE_FLOATS (A_SM_FLOATS + B_SM_FLOATS)     // 9728
#define NSTAGE 2
#define SMEM_BYTES (NSTAGE * STAGE_FLOATS * 4)       // 77824 (76 KB) -> 2 CTAs/SM

// within-8-block k permutation: logical k -> physical offset
// off(k) = 2*(k&3) + ((k>>2)&1)   (logical pair (t, t+4) -> adjacent (2t, 2t+1))
__host__ __device__ __forceinline__ int kperm8(int k) {
    return 2 * (k & 3) + ((k >> 2) & 1);
}

// ---------------------------------------------------------------------------
// Scratch (__device__ globals: allocation-free)
// ---------------------------------------------------------------------------
__device__ __align__(256) float g_dhf[(size_t)NROWS * INF];   // hat_d*feature, tf32-rounded
__device__ __align__(256) float g_wrn[(size_t)OUTF * INF];    // W, tf32-rounded, k-permuted
__device__ __align__(256) float g_gT [(size_t)OUTF * NROWS];  // g^T, tf32-rounded, k-permuted

// ---------------------------------------------------------------------------
// Helpers
// ---------------------------------------------------------------------------
__device__ __forceinline__ uint32_t smem_u32(const void* p) {
    uint32_t a;
    asm("{ .reg .u64 t; cvta.to.shared.u64 t, %1; cvt.u32.u64 %0, t; }" : "=r"(a) : "l"(p));
    return a;
}

__device__ __forceinline__ float rna_tf32(float x) {
    uint32_t u;
    asm("cvt.rna.tf32.f32 %0, %1;" : "=r"(u) : "f"(x));
    return __uint_as_float(u);
}

__device__ __forceinline__ void cp16(uint32_t dst_smem, const float* src) {
    asm volatile("cp.async.cg.shared.global [%0], [%1], 16;"
                 :: "r"(dst_smem), "l"(src) : "memory");
}

__device__ __forceinline__ void mma_tf32(float* d, const uint32_t* a, const uint32_t* b) {
    asm volatile(
        "mma.sync.aligned.m16n8k8.row.col.f32.tf32.tf32.f32 "
        "{%0,%1,%2,%3}, {%4,%5,%6,%7}, {%8,%9}, {%0,%1,%2,%3};"
        : "+f"(d[0]), "+f"(d[1]), "+f"(d[2]), "+f"(d[3])
        : "r"(a[0]), "r"(a[1]), "r"(a[2]), "r"(a[3]),
          "r"(b[0]), "r"(b[1]));
}

// ---------------------------------------------------------------------------
// Prep: dhf = rna(hat_d * feature);  wrn[r][kperm] = rna(W[r][k])
// ---------------------------------------------------------------------------
__global__ void prep_kernel(const float* __restrict__ hat_d,
                            const float* __restrict__ feature,
                            const float* __restrict__ W) {
    size_t i = (size_t)blockIdx.x * blockDim.x + threadIdx.x;
    size_t stride = (size_t)gridDim.x * blockDim.x;

    const float4* f4 = reinterpret_cast<const float4*>(feature);
    float4* d4 = reinterpret_cast<float4*>(g_dhf);
    size_t total4 = (size_t)NROWS * INF / 4;
    for (size_t idx = i; idx < total4; idx += stride) {
        float4 f = f4[idx];
        float d = __ldg(hat_d + (idx >> 7));
        float4 o;
        o.x = rna_tf32(d * f.x);
        o.y = rna_tf32(d * f.y);
        o.z = rna_tf32(d * f.z);
        o.w = rna_tf32(d * f.w);
        d4[idx] = o;
    }

    size_t wtotal = (size_t)OUTF * INF;
    for (size_t idx = i; idx < wtotal; idx += stride) {
        int k = (int)(idx & (INF - 1));
        size_t row = idx >> 9;
        int kp = (k & ~7) | kperm8(k & 7);
        g_wrn[row * INF + kp] = rna_tf32(W[idx]);
    }
}

// ---------------------------------------------------------------------------
// tf32 mma.sync GEMM: D[128 x 128] = Atile[128 x K] @ Btile[128 x K]^T
//   B (global) is k-PERMUTED within 8-blocks; A natural layout.
//   mode 0: g_gT[n][perm(m)] = rna(D[m][n])                        (GEMM1)
//   mode 1: out[m][n] = hat_d[m]*(D[m][n] + gT[n][perm(m)]) + b[n] (GEMM2)
// 256 threads = 8 warps in 4(M) x 2(N) grid; warp tile 32 x 64.
// 2 CTAs per SM for cross-CTA latency/sync hiding.
// ---------------------------------------------------------------------------
__global__ void __launch_bounds__(256, 2)
gemm_tf32_kernel(const float* __restrict__ Ap, int a_ld,
                 const float* __restrict__ Bp, int b_ld,
                 int nstages, int mode,
                 const float* __restrict__ hat_d,
                 const float* __restrict__ bias,
                 float* __restrict__ out)
{
    extern __shared__ float sm[];
    const int tid = threadIdx.x;
    const int mtile = blockIdx.x;
    const int ntile = blockIdx.y;
    const int wid = tid >> 5;
    const int lane = tid & 31;
    const int wm = wid & 3;           // 0..3: M position (32 rows each)
    const int wn = wid >> 2;          // 0..1: N position (64 cols each)
    const int g = lane >> 2;          // groupID 0..7
    const int t = lane & 3;           // threadID in group 0..3

    float acc[2][8][4];
    #pragma unroll
    for (int mi = 0; mi < 2; ++mi)
        #pragma unroll
        for (int ni = 0; ni < 8; ++ni)
            #pragma unroll
            for (int r = 0; r < 4; ++r)
                acc[mi][ni][r] = 0.0f;

    const float* Agm = Ap + (size_t)mtile * TILE_M * a_ld;
    const float* Bgm = Bp + (size_t)ntile * TILE_N * b_ld;

    // ---- stage loader: A 1024 float4s + B 1024 float4s across 256 threads ----
    auto load_stage = [&](int s) {
        const int buf = s & 1;
        float* As = sm + buf * STAGE_FLOATS;
        float* Bs = As + A_SM_FLOATS;
        const int k0 = s * KC;
        #pragma unroll
        for (int i = 0; i < 4; ++i) {
            int v = tid + i * 256;
            int row = v >> 3, j = v & 7;
            cp16(smem_u32(As + row * PA + j * 4),
                 Agm + (size_t)row * a_ld + k0 + j * 4);
        }
        #pragma unroll
        for (int i = 0; i < 4; ++i) {
            int v = tid + i * 256;
            int row = v >> 3, j = v & 7;
            cp16(smem_u32(Bs + row * PB + j * 4),
                 Bgm + (size_t)row * b_ld + k0 + j * 4);
        }
    };

    // prologue: stage 0 in flight
    load_stage(0);
    asm volatile("cp.async.commit_group;" ::: "memory");

    for (int s = 0; s < nstages; ++s) {
        if (s + 1 < nstages) load_stage(s + 1);
        asm volatile("cp.async.commit_group;" ::: "memory");   // empty group ok
        asm volatile("cp.async.wait_group 1;" ::: "memory");   // stage s resident
        __syncthreads();

        const int buf = s & 1;
        const float* As = sm + buf * STAGE_FLOATS;
        const float* Bs = As + A_SM_FLOATS;
        const float* Abase = As + (wm * 32 + g) * PA + t;
        const float* Bbase = Bs + (wn * 64 + g) * PB + 2 * t;

        #pragma unroll
        for (int kk = 0; kk < KC; kk += 8) {
            uint32_t a[2][4], b[8][2];
            #pragma unroll
            for (int mi = 0; mi < 2; ++mi) {
                const float* p = Abase + mi * 16 * PA + kk;
                a[mi][0] = __float_as_uint(p[0]);
                a[mi][1] = __float_as_uint(p[8 * PA]);
                a[mi][2] = __float_as_uint(p[4]);
                a[mi][3] = __float_as_uint(p[8 * PA + 4]);
            }
            #pragma unroll
            for (int ni = 0; ni < 8; ++ni) {
                float2 v = *reinterpret_cast<const float2*>(Bbase + ni * 8 * PB + kk);
                b[ni][0] = __float_as_uint(v.x);
                b[ni][1] = __float_as_uint(v.y);
            }
            #pragma unroll
            for (int mi = 0; mi < 2; ++mi)
                #pragma unroll
                for (int ni = 0; ni < 8; ++ni)
                    mma_tf32(acc[mi][ni], a[mi], b[ni]);
        }
        __syncthreads();   // readers done before next iter's loads overwrite buf
    }

    // ---- epilogue ----
    const int mbase = mtile * TILE_M + wm * 32;
    const int nbase = ntile * TILE_N + wn * 64;
    const int pg = kperm8(g);   // permuted within-8-block row offset

    if (mode == 0) {
        #pragma unroll
        for (int mi = 0; mi < 2; ++mi) {
            int r0p = mbase + mi * 16 + pg;   // (mbase+mi*16) is 8-aligned
            int r1p = r0p + 8;
            #pragma unroll
            for (int ni = 0; ni < 8; ++ni) {
                int c0 = nbase + ni * 8 + 2 * t;
                int c1 = c0 + 1;
                g_gT[(size_t)c0 * NROWS + r0p] = rna_tf32(acc[mi][ni][0]);
                g_gT[(size_t)c1 * NROWS + r0p] = rna_tf32(acc[mi][ni][1]);
                g_gT[(size_t)c0 * NROWS + r1p] = rna_tf32(acc[mi][ni][2]);
                g_gT[(size_t)c1 * NROWS + r1p] = rna_tf32(acc[mi][ni][3]);
            }
        }
    } else {
        #pragma unroll
        for (int mi = 0; mi < 2; ++mi) {
            int r0 = mbase + mi * 16 + g;     // logical output row
            int r1 = r0 + 8;
            int r0p = mbase + mi * 16 + pg;   // permuted gT column
            int r1p = r0p + 8;
            float h0 = __ldg(hat_d + r0);
            float h1 = __ldg(hat_d + r1);
            #pragma unroll
            for (int ni = 0; ni < 8; ++ni) {
                int c0 = nbase + ni * 8 + 2 * t;
                int c1 = c0 + 1;
                float b0v = __ldg(bias + c0);
                float b1v = __ldg(bias + c1);
                float g00 = g_gT[(size_t)c0 * NROWS + r0p];
                float g01 = g_gT[(size_t)c1 * NROWS + r0p];
                float g10 = g_gT[(size_t)c0 * NROWS + r1p];
                float g11 = g_gT[(size_t)c1 * NROWS + r1p];
                float2 v0, v1;
                v0.x = fmaf(h0, acc[mi][ni][0] + g00, b0v);
                v0.y = fmaf(h0, acc[mi][ni][1] + g01, b1v);
                v1.x = fmaf(h1, acc[mi][ni][2] + g10, b0v);
                v1.y = fmaf(h1, acc[mi][ni][3] + g11, b1v);
                *reinterpret_cast<float2*>(out + (size_t)r0 * OUTF + c0) = v0;
                *reinterpret_cast<float2*>(out + (size_t)r1 * OUTF + c0) = v1;
            }
        }
    }
}

// ---------------------------------------------------------------------------
// Host side
// ---------------------------------------------------------------------------
extern "C" void kernel_launch(void* const* d_in, const int* in_sizes, int n_in,
                              void* d_out, int out_size) {
    const float *A = nullptr, *hat_d = nullptr, *feature = nullptr,
                *W = nullptr, *b = nullptr;
    for (int i = 0; i < n_in; ++i) {
        switch (in_sizes[i]) {
            case NROWS:       hat_d   = (const float*)d_in[i]; break;   // 16384
            case OUTF:        b       = (const float*)d_in[i]; break;   // 256
            case OUTF * INF:  W       = (const float*)d_in[i]; break;   // 131072
            case NROWS * INF: feature = (const float*)d_in[i]; break;   // 8388608
            default:          A       = (const float*)d_in[i]; break;   // 16384*16384
        }
    }

    void *p_dhf = nullptr, *p_wrn = nullptr, *p_gT = nullptr;
    cudaGetSymbolAddress(&p_dhf, g_dhf);
    cudaGetSymbolAddress(&p_wrn, g_wrn);
    cudaGetSymbolAddress(&p_gT,  g_gT);

    static bool attr_set = false;
    if (!attr_set) {
        cudaFuncSetAttribute(gemm_tf32_kernel,
                             cudaFuncAttributeMaxDynamicSharedMemorySize, SMEM_BYTES);
        attr_set = true;
    }

    prep_kernel<<<1024, 256>>>(hat_d, feature, W);

    // GEMM1: g^T = (dhf @ W^T)^T   K = 512 -> 16 stages  (B = wrn, k-permuted)
    gemm_tf32_kernel<<<dim3(NROWS / TILE_M, OUTF / TILE_N), 256, SMEM_BYTES>>>(
        (const float*)p_dhf, INF,
        (const float*)p_wrn, INF,
        INF / KC, 0, nullptr, nullptr, nullptr);

    // GEMM2: out = hat_d*(A@g + g) + b   K = 16384 -> 512 stages  (B = gT, k-permuted)
    gemm_tf32_kernel<<<dim3(NROWS / TILE_M, OUTF / TILE_N), 256, SMEM_BYTES>>>(
        A, NROWS,
        (const float*)p_gT, NROWS,
        NROWS / KC, 1, hat_d, b, (float*)d_out);

    (void)out_size;
}